// round 13
// baseline (speedup 1.0000x reference)
#include <cuda_runtime.h>
#include <math.h>

#define N_NODES 100000
#define N_EDGES 3200000
#define F_IN    256
#define U       32
#define C       40

#define SCAN_CH   512
#define SCAN_NB   ((N_NODES + SCAN_CH - 1) / SCAN_CH)   // 196

// ---- scratch (device globals; no allocations allowed) ----
__device__ int   g_degout_i[N_NODES];
__device__ int   g_degin_i[N_NODES];
__device__ float g_invout[N_NODES];
__device__ float g_invin[N_NODES];
__device__ int   g_part[SCAN_NB];
__device__ int   g_off[N_NODES + 1];
__device__ int   g_cursor[N_NODES];
__device__ int   g_esrc[N_EDGES];
__device__ __align__(16) float g_h1[(size_t)N_NODES * U];   // (x * d_out^-1/2) @ W1
__device__ __align__(16) float g_h2[(size_t)N_NODES * C];   // (relu(L1) * d_out^-1/2) @ W2

// ---------------------------------------------------------------------------
__global__ void zero_deg_kernel() {
    int i = blockIdx.x * blockDim.x + threadIdx.x;
    if (i < N_NODES) { g_degout_i[i] = 0; g_degin_i[i] = 0; }
}

__global__ void hist_kernel(const int* __restrict__ src, const int* __restrict__ dst) {
    int e = blockIdx.x * blockDim.x + threadIdx.x;
    if (e >= N_EDGES) return;
    atomicAdd(&g_degout_i[src[e]], 1);
    atomicAdd(&g_degin_i[dst[e]], 1);
}

__global__ void invsqrt_kernel() {
    int n = blockIdx.x * blockDim.x + threadIdx.x;
    if (n >= N_NODES) return;
    g_invout[n] = rsqrtf(fmaxf((float)g_degout_i[n], 1.0f));
    g_invin[n]  = rsqrtf(fmaxf((float)g_degin_i[n],  1.0f));
}

// ---------------------------------------------------------------------------
// GEMM1 via tf32 tensor cores, single MMA (no hi/lo split — input rounding
// error ~5e-4/element averages to ~1e-6 in the final output, vs 1e-3 budget).
// Block = 128 threads (4 warps), tile = 64 nodes x 32 u, K chunks of 32.
#define TILE_N 64
#define KT2    32
#define ASTR   36     // a-frag LDS bank = (4r + c) % 32 -> conflict-free
#define BSTR   40     // b-frag LDS bank = (8k + n) % 32 -> conflict-free

__device__ __forceinline__ unsigned f2tf(float f) {
    unsigned r; asm("cvt.rna.tf32.f32 %0, %1;" : "=r"(r) : "f"(f)); return r;
}
__device__ __forceinline__ void mma_tf32(float* d, const unsigned* a, const unsigned* b) {
    asm("mma.sync.aligned.m16n8k8.row.col.f32.tf32.tf32.f32 "
        "{%0,%1,%2,%3}, {%4,%5,%6,%7}, {%8,%9}, {%0,%1,%2,%3};"
        : "+f"(d[0]), "+f"(d[1]), "+f"(d[2]), "+f"(d[3])
        : "r"(a[0]), "r"(a[1]), "r"(a[2]), "r"(a[3]), "r"(b[0]), "r"(b[1]));
}

__global__ void __launch_bounds__(128) gemm1_kernel(const float* __restrict__ x,
                                                    const float* __restrict__ W1) {
    __shared__ unsigned sA[TILE_N * ASTR];
    __shared__ unsigned sB[KT2 * BSTR];

    const int t = threadIdx.x;
    const int warp = t >> 5, lane = t & 31;
    const int n0blk = blockIdx.x * TILE_N;
    const int r = lane >> 2, c = lane & 3;    // a-frag / d-frag coords
    const int m0 = warp * 16;

    float d[4][4] = {};    // [n-tile][frag]

    for (int k0 = 0; k0 < F_IN; k0 += KT2) {
        // ---- stage x tile (64 x 32) as tf32 ----
        for (int i = t; i < TILE_N * (KT2 / 4); i += 128) {   // 512 float4s
            int row = i >> 3, c4 = i & 7;
            int gn = n0blk + row;
            float4 v = make_float4(0.f, 0.f, 0.f, 0.f);
            if (gn < N_NODES) v = *(const float4*)&x[(size_t)gn * F_IN + k0 + c4 * 4];
            uint4 hv = make_uint4(f2tf(v.x), f2tf(v.y), f2tf(v.z), f2tf(v.w));
            *(uint4*)&sA[row * ASTR + c4 * 4] = hv;    // row*36*4B is 16B-aligned
        }
        // ---- stage W1 tile (32 x 32) as tf32 ----
        for (int i = t; i < KT2 * (U / 4); i += 128) {        // 256 float4s
            int k = i >> 3, c4 = i & 7;
            float4 v = *(const float4*)&W1[(size_t)(k0 + k) * U + c4 * 4];
            uint4 hv = make_uint4(f2tf(v.x), f2tf(v.y), f2tf(v.z), f2tf(v.w));
            *(uint4*)&sB[k * BSTR + c4 * 4] = hv;      // k*40*4B is 16B-aligned
        }
        __syncthreads();

#pragma unroll
        for (int ks = 0; ks < KT2 / 8; ks++) {
            const int kk = ks * 8;
            unsigned a[4];
            const int abase = (m0 + r) * ASTR + kk + c;
            a[0] = sA[abase];            a[1] = sA[abase + 8 * ASTR];
            a[2] = sA[abase + 4];        a[3] = sA[abase + 8 * ASTR + 4];
#pragma unroll
            for (int nt = 0; nt < 4; nt++) {
                unsigned b[2];
                const int bbase = (kk + c) * BSTR + nt * 8 + r;   // b: k=c(lane%4), n=r(lane>>2)
                b[0] = sB[bbase];            b[1] = sB[bbase + 4 * BSTR];
                mma_tf32(d[nt], a, b);
            }
        }
        __syncthreads();
    }

    // ---- epilogue: scale by invout, write 2 rows x 4 n-tiles as float2 ----
    const int n1 = n0blk + m0 + r;
    const int n2 = n1 + 8;
    const float s1 = (n1 < N_NODES) ? g_invout[n1] : 0.f;
    const float s2 = (n2 < N_NODES) ? g_invout[n2] : 0.f;
#pragma unroll
    for (int nt = 0; nt < 4; nt++) {
        const int u = nt * 8 + c * 2;
        if (n1 < N_NODES) {
            float2 o; o.x = d[nt][0] * s1; o.y = d[nt][1] * s1;
            *(float2*)&g_h1[(size_t)n1 * U + u] = o;
        }
        if (n2 < N_NODES) {
            float2 o; o.x = d[nt][2] * s2; o.y = d[nt][3] * s2;
            *(float2*)&g_h1[(size_t)n2 * U + u] = o;
        }
    }
}

// ---------------------------------------------------------------------------
__global__ void __launch_bounds__(SCAN_CH) scan_part_kernel() {
    __shared__ int sw[SCAN_CH / 32];
    const int t = threadIdx.x;
    const int i = blockIdx.x * SCAN_CH + t;
    int v = (i < N_NODES) ? g_degin_i[i] : 0;
#pragma unroll
    for (int o = 16; o; o >>= 1) v += __shfl_xor_sync(0xffffffffu, v, o);
    if ((t & 31) == 0) sw[t >> 5] = v;
    __syncthreads();
    if (t < SCAN_CH / 32) {
        int s = sw[t];
#pragma unroll
        for (int o = SCAN_CH / 64; o; o >>= 1) s += __shfl_xor_sync(0xffffffffu, s, o);
        if (t == 0) g_part[blockIdx.x] = s;
    }
}

__global__ void scan_mid_kernel() {
    __shared__ int s[256];
    const int t = threadIdx.x;
    int v = (t < SCAN_NB) ? g_part[t] : 0;
    s[t] = v;
    __syncthreads();
#pragma unroll
    for (int off = 1; off < 256; off <<= 1) {
        int u = (t >= off) ? s[t - off] : 0;
        __syncthreads();
        s[t] += u;
        __syncthreads();
    }
    if (t < SCAN_NB) g_part[t] = s[t] - v;
}

__global__ void __launch_bounds__(SCAN_CH) scan_write_kernel() {
    __shared__ int s[SCAN_CH];
    const int t = threadIdx.x;
    const int i = blockIdx.x * SCAN_CH + t;
    int v = (i < N_NODES) ? g_degin_i[i] : 0;
    s[t] = v;
    __syncthreads();
#pragma unroll
    for (int off = 1; off < SCAN_CH; off <<= 1) {
        int u = (t >= off) ? s[t - off] : 0;
        __syncthreads();
        s[t] += u;
        __syncthreads();
    }
    if (i < N_NODES) {
        int off = g_part[blockIdx.x] + s[t] - v;
        g_off[i] = off;
        g_cursor[i] = off;
    }
    if (i == 0) g_off[N_NODES] = N_EDGES;
}

__global__ void reorder_kernel(const int* __restrict__ src, const int* __restrict__ dst) {
    int e = blockIdx.x * blockDim.x + threadIdx.x;
    if (e >= N_EDGES) return;
    int pos = atomicAdd(&g_cursor[dst[e]], 1);
    g_esrc[pos] = src[e];
}

// ---------------------------------------------------------------------------
// Aggregation layer 1 + relu + GEMM2, fused (R11 structure, unchanged).
__global__ void __launch_bounds__(256) agg1_kernel(const float* __restrict__ b1,
                                                   const float* __restrict__ W2) {
    __shared__ float sW2[U * C];
    for (int i = threadIdx.x; i < U * C; i += 256) sW2[i] = W2[i];
    __syncthreads();

    const int n = (blockIdx.x * blockDim.x + threadIdx.x) >> 5;
    const int lane = threadIdx.x & 31;
    if (n >= N_NODES) return;
    const int slot = lane >> 3;
    const int q    = lane & 7;
    const int start = g_off[n], end = g_off[n + 1];

    float4 a4 = make_float4(0.f, 0.f, 0.f, 0.f);
    int e = start;
    while (e + 32 <= end) {
        int sv = g_esrc[e + lane];
#pragma unroll
        for (int i = 0; i < 8; i++) {
            int s = __shfl_sync(0xffffffffu, sv, 4 * i + slot);
            float4 v = *(const float4*)&g_h1[(size_t)s * U + 4 * q];
            a4.x += v.x; a4.y += v.y; a4.z += v.z; a4.w += v.w;
        }
        e += 32;
    }
    if (e < end) {
        const int rem = end - e;
        const int idx = e + lane;
        int sv = g_esrc[idx < end ? idx : end - 1];
        const int steps = (rem + 3) >> 2;
        for (int i = 0; i < steps; i++) {
            int s = __shfl_sync(0xffffffffu, sv, 4 * i + slot);
            float4 v = *(const float4*)&g_h1[(size_t)s * U + 4 * q];
            if (4 * i + slot < rem) { a4.x += v.x; a4.y += v.y; a4.z += v.z; a4.w += v.w; }
        }
    }
#pragma unroll
    for (int o = 8; o <= 16; o <<= 1) {
        a4.x += __shfl_xor_sync(0xffffffffu, a4.x, o);
        a4.y += __shfl_xor_sync(0xffffffffu, a4.y, o);
        a4.z += __shfl_xor_sync(0xffffffffu, a4.z, o);
        a4.w += __shfl_xor_sync(0xffffffffu, a4.w, o);
    }

    const int srcl = lane >> 2;
    float cx = __shfl_sync(0xffffffffu, a4.x, srcl);
    float cy = __shfl_sync(0xffffffffu, a4.y, srcl);
    float cz = __shfl_sync(0xffffffffu, a4.z, srcl);
    float cw = __shfl_sync(0xffffffffu, a4.w, srcl);
    const int comp = lane & 3;
    float accf = (comp == 0) ? cx : (comp == 1) ? cy : (comp == 2) ? cz : cw;

    const float v = fmaxf(accf * g_invin[n] + b1[lane], 0.f);

    float o0 = 0.f, o1 = 0.f;
#pragma unroll
    for (int k = 0; k < U; k++) {
        float h = __shfl_sync(0xffffffffu, v, k);
        o0 += h * sW2[k * C + lane];
        if (lane < 8) o1 += h * sW2[k * C + 32 + lane];
    }
    const float so = g_invout[n];
    g_h2[(size_t)n * C + lane] = o0 * so;
    if (lane < 8) g_h2[(size_t)n * C + 32 + lane] = o1 * so;
}

// ---------------------------------------------------------------------------
// Aggregation layer 2 (R11 structure, unchanged).
__global__ void agg2_kernel(float* __restrict__ out, const float* __restrict__ b2) {
    const int n = (blockIdx.x * blockDim.x + threadIdx.x) >> 5;
    const int lane = threadIdx.x & 31;
    if (n >= N_NODES) return;
    const int start = g_off[n], end = g_off[n + 1];
    const bool act = lane < 20;

    float ax = 0.f, ay = 0.f;
    int e = start;
    while (e + 32 <= end) {
        int sv = g_esrc[e + lane];
#pragma unroll
        for (int i = 0; i < 32; i++) {
            int s = __shfl_sync(0xffffffffu, sv, i);
            if (act) {
                float2 v = *(const float2*)&g_h2[(size_t)s * C + 2 * lane];
                ax += v.x; ay += v.y;
            }
        }
        e += 32;
    }
    if (e < end) {
        int rem = end - e;
        int sv = (lane < rem) ? g_esrc[e + lane] : 0;
        for (int i = 0; i < rem; i++) {
            int s = __shfl_sync(0xffffffffu, sv, i);
            if (act) {
                float2 v = *(const float2*)&g_h2[(size_t)s * C + 2 * lane];
                ax += v.x; ay += v.y;
            }
        }
    }

    const float inv = g_invin[n];
    const float NEG_INF = __int_as_float(0xff800000);
    float v0 = act ? (ax * inv + b2[2 * lane])     : NEG_INF;
    float v1 = act ? (ay * inv + b2[2 * lane + 1]) : NEG_INF;

    float m = fmaxf(v0, v1);
#pragma unroll
    for (int o = 16; o; o >>= 1) m = fmaxf(m, __shfl_xor_sync(0xffffffffu, m, o));
    float se = act ? (expf(v0 - m) + expf(v1 - m)) : 0.f;
#pragma unroll
    for (int o = 16; o; o >>= 1) se += __shfl_xor_sync(0xffffffffu, se, o);
    const float ls = logf(se);

    if (act) {
        float2 o;
        o.x = v0 - m - ls;
        o.y = v1 - m - ls;
        *(float2*)&out[(size_t)n * C + 2 * lane] = o;
    }
}

// ---------------------------------------------------------------------------
extern "C" void kernel_launch(void* const* d_in, const int* in_sizes, int n_in,
                              void* d_out, int out_size) {
    const float* x   = (const float*)d_in[0];
    const float* W1  = (const float*)d_in[1];
    const float* b1  = (const float*)d_in[2];
    const float* W2  = (const float*)d_in[3];
    const float* b2  = (const float*)d_in[4];
    const int*   src = (const int*)d_in[5];
    const int*   dst = (const int*)d_in[6];
    float* out = (float*)d_out;

    zero_deg_kernel<<<(N_NODES + 255) / 256, 256>>>();
    hist_kernel<<<(N_EDGES + 255) / 256, 256>>>(src, dst);
    invsqrt_kernel<<<(N_NODES + 255) / 256, 256>>>();
    gemm1_kernel<<<(N_NODES + TILE_N - 1) / TILE_N, 128>>>(x, W1);   // slot #4 -> profiled
    scan_part_kernel<<<SCAN_NB, SCAN_CH>>>();
    scan_mid_kernel<<<1, 256>>>();
    scan_write_kernel<<<SCAN_NB, SCAN_CH>>>();
    reorder_kernel<<<(N_EDGES + 255) / 256, 256>>>(src, dst);
    agg1_kernel<<<(N_NODES * 32 + 255) / 256, 256>>>(b1, W2);
    agg2_kernel<<<(N_NODES * 32 + 255) / 256, 256>>>(out, b2);
}

// round 14
// speedup vs baseline: 1.3762x; 1.3762x over previous
#include <cuda_runtime.h>
#include <math.h>

#define N_NODES 100000
#define N_EDGES 3200000
#define F_IN    256
#define U       32
#define C       40

#define SCAN_CH   512
#define SCAN_NB   ((N_NODES + SCAN_CH - 1) / SCAN_CH)   // 196

// ---- scratch (device globals; no allocations allowed) ----
__device__ int   g_degout_i[N_NODES];
__device__ int   g_degin_i[N_NODES];
__device__ float g_invout[N_NODES];
__device__ float g_invin[N_NODES];
__device__ int   g_part[SCAN_NB];
__device__ int   g_off[N_NODES + 1];
__device__ int   g_cursor[N_NODES];
__device__ int   g_esrc[N_EDGES];
__device__ __align__(16) float g_h1[(size_t)N_NODES * U];   // (x * d_out^-1/2) @ W1
__device__ __align__(16) float g_h2[(size_t)N_NODES * C];   // (relu(L1) * d_out^-1/2) @ W2

// ---------------------------------------------------------------------------
__global__ void zero_deg_kernel() {
    int i = blockIdx.x * blockDim.x + threadIdx.x;
    if (i < N_NODES) { g_degout_i[i] = 0; g_degin_i[i] = 0; }
}

__global__ void hist_kernel(const int* __restrict__ src, const int* __restrict__ dst) {
    int e = blockIdx.x * blockDim.x + threadIdx.x;
    if (e >= N_EDGES) return;
    atomicAdd(&g_degout_i[src[e]], 1);
    atomicAdd(&g_degin_i[dst[e]], 1);
}

__global__ void invsqrt_kernel() {
    int n = blockIdx.x * blockDim.x + threadIdx.x;
    if (n >= N_NODES) return;
    g_invout[n] = rsqrtf(fmaxf((float)g_degout_i[n], 1.0f));
    g_invin[n]  = rsqrtf(fmaxf((float)g_degin_i[n],  1.0f));
}

// ---------------------------------------------------------------------------
// GEMM1 via tf32 tensor cores, single MMA (no hi/lo split — input rounding
// error ~5e-4/element averages to ~1e-6 in the final output, vs 1e-3 budget).
// Block = 128 threads (4 warps), tile = 64 nodes x 32 u, K chunks of 32.
#define TILE_N 64
#define KT2    32
#define ASTR   36     // a-frag LDS bank = (4r + c) % 32 -> conflict-free
#define BSTR   40     // b-frag LDS bank = (8k + n) % 32 -> conflict-free

__device__ __forceinline__ unsigned f2tf(float f) {
    unsigned r; asm("cvt.rna.tf32.f32 %0, %1;" : "=r"(r) : "f"(f)); return r;
}
__device__ __forceinline__ void mma_tf32(float* d, const unsigned* a, const unsigned* b) {
    asm("mma.sync.aligned.m16n8k8.row.col.f32.tf32.tf32.f32 "
        "{%0,%1,%2,%3}, {%4,%5,%6,%7}, {%8,%9}, {%0,%1,%2,%3};"
        : "+f"(d[0]), "+f"(d[1]), "+f"(d[2]), "+f"(d[3])
        : "r"(a[0]), "r"(a[1]), "r"(a[2]), "r"(a[3]), "r"(b[0]), "r"(b[1]));
}

__global__ void __launch_bounds__(128) gemm1_kernel(const float* __restrict__ x,
                                                    const float* __restrict__ W1) {
    __shared__ unsigned sA[TILE_N * ASTR];
    __shared__ unsigned sB[KT2 * BSTR];

    const int t = threadIdx.x;
    const int warp = t >> 5, lane = t & 31;
    const int n0blk = blockIdx.x * TILE_N;
    const int r = lane >> 2, c = lane & 3;    // a-frag / d-frag coords
    const int m0 = warp * 16;

    float d[4][4] = {};    // [n-tile][frag]

    for (int k0 = 0; k0 < F_IN; k0 += KT2) {
        // ---- stage x tile (64 x 32) as tf32 ----
        for (int i = t; i < TILE_N * (KT2 / 4); i += 128) {   // 512 float4s
            int row = i >> 3, c4 = i & 7;
            int gn = n0blk + row;
            float4 v = make_float4(0.f, 0.f, 0.f, 0.f);
            if (gn < N_NODES) v = *(const float4*)&x[(size_t)gn * F_IN + k0 + c4 * 4];
            uint4 hv = make_uint4(f2tf(v.x), f2tf(v.y), f2tf(v.z), f2tf(v.w));
            *(uint4*)&sA[row * ASTR + c4 * 4] = hv;    // row*36*4B is 16B-aligned
        }
        // ---- stage W1 tile (32 x 32) as tf32 ----
        for (int i = t; i < KT2 * (U / 4); i += 128) {        // 256 float4s
            int k = i >> 3, c4 = i & 7;
            float4 v = *(const float4*)&W1[(size_t)(k0 + k) * U + c4 * 4];
            uint4 hv = make_uint4(f2tf(v.x), f2tf(v.y), f2tf(v.z), f2tf(v.w));
            *(uint4*)&sB[k * BSTR + c4 * 4] = hv;      // k*40*4B is 16B-aligned
        }
        __syncthreads();

#pragma unroll
        for (int ks = 0; ks < KT2 / 8; ks++) {
            const int kk = ks * 8;
            unsigned a[4];
            const int abase = (m0 + r) * ASTR + kk + c;
            a[0] = sA[abase];            a[1] = sA[abase + 8 * ASTR];
            a[2] = sA[abase + 4];        a[3] = sA[abase + 8 * ASTR + 4];
#pragma unroll
            for (int nt = 0; nt < 4; nt++) {
                unsigned b[2];
                const int bbase = (kk + c) * BSTR + nt * 8 + r;   // b: k=c(lane%4), n=r(lane>>2)
                b[0] = sB[bbase];            b[1] = sB[bbase + 4 * BSTR];
                mma_tf32(d[nt], a, b);
            }
        }
        __syncthreads();
    }

    // ---- epilogue: scale by invout, write 2 rows x 4 n-tiles as float2 ----
    const int n1 = n0blk + m0 + r;
    const int n2 = n1 + 8;
    const float s1 = (n1 < N_NODES) ? g_invout[n1] : 0.f;
    const float s2 = (n2 < N_NODES) ? g_invout[n2] : 0.f;
#pragma unroll
    for (int nt = 0; nt < 4; nt++) {
        const int u = nt * 8 + c * 2;
        if (n1 < N_NODES) {
            float2 o; o.x = d[nt][0] * s1; o.y = d[nt][1] * s1;
            *(float2*)&g_h1[(size_t)n1 * U + u] = o;
        }
        if (n2 < N_NODES) {
            float2 o; o.x = d[nt][2] * s2; o.y = d[nt][3] * s2;
            *(float2*)&g_h1[(size_t)n2 * U + u] = o;
        }
    }
}

// ---------------------------------------------------------------------------
__global__ void __launch_bounds__(SCAN_CH) scan_part_kernel() {
    __shared__ int sw[SCAN_CH / 32];
    const int t = threadIdx.x;
    const int i = blockIdx.x * SCAN_CH + t;
    int v = (i < N_NODES) ? g_degin_i[i] : 0;
#pragma unroll
    for (int o = 16; o; o >>= 1) v += __shfl_xor_sync(0xffffffffu, v, o);
    if ((t & 31) == 0) sw[t >> 5] = v;
    __syncthreads();
    if (t < SCAN_CH / 32) {
        int s = sw[t];
#pragma unroll
        for (int o = SCAN_CH / 64; o; o >>= 1) s += __shfl_xor_sync(0xffffffffu, s, o);
        if (t == 0) g_part[blockIdx.x] = s;
    }
}

__global__ void scan_mid_kernel() {
    __shared__ int s[256];
    const int t = threadIdx.x;
    int v = (t < SCAN_NB) ? g_part[t] : 0;
    s[t] = v;
    __syncthreads();
#pragma unroll
    for (int off = 1; off < 256; off <<= 1) {
        int u = (t >= off) ? s[t - off] : 0;
        __syncthreads();
        s[t] += u;
        __syncthreads();
    }
    if (t < SCAN_NB) g_part[t] = s[t] - v;
}

__global__ void __launch_bounds__(SCAN_CH) scan_write_kernel() {
    __shared__ int s[SCAN_CH];
    const int t = threadIdx.x;
    const int i = blockIdx.x * SCAN_CH + t;
    int v = (i < N_NODES) ? g_degin_i[i] : 0;
    s[t] = v;
    __syncthreads();
#pragma unroll
    for (int off = 1; off < SCAN_CH; off <<= 1) {
        int u = (t >= off) ? s[t - off] : 0;
        __syncthreads();
        s[t] += u;
        __syncthreads();
    }
    if (i < N_NODES) {
        int off = g_part[blockIdx.x] + s[t] - v;
        g_off[i] = off;
        g_cursor[i] = off;
    }
    if (i == 0) g_off[N_NODES] = N_EDGES;
}

__global__ void reorder_kernel(const int* __restrict__ src, const int* __restrict__ dst) {
    int e = blockIdx.x * blockDim.x + threadIdx.x;
    if (e >= N_EDGES) return;
    int pos = atomicAdd(&g_cursor[dst[e]], 1);
    g_esrc[pos] = src[e];
}

// ---------------------------------------------------------------------------
// Aggregation layer 1 + relu + GEMM2, fused (R11 structure, unchanged).
__global__ void __launch_bounds__(256) agg1_kernel(const float* __restrict__ b1,
                                                   const float* __restrict__ W2) {
    __shared__ float sW2[U * C];
    for (int i = threadIdx.x; i < U * C; i += 256) sW2[i] = W2[i];
    __syncthreads();

    const int n = (blockIdx.x * blockDim.x + threadIdx.x) >> 5;
    const int lane = threadIdx.x & 31;
    if (n >= N_NODES) return;
    const int slot = lane >> 3;
    const int q    = lane & 7;
    const int start = g_off[n], end = g_off[n + 1];

    float4 a4 = make_float4(0.f, 0.f, 0.f, 0.f);
    int e = start;
    while (e + 32 <= end) {
        int sv = g_esrc[e + lane];
#pragma unroll
        for (int i = 0; i < 8; i++) {
            int s = __shfl_sync(0xffffffffu, sv, 4 * i + slot);
            float4 v = *(const float4*)&g_h1[(size_t)s * U + 4 * q];
            a4.x += v.x; a4.y += v.y; a4.z += v.z; a4.w += v.w;
        }
        e += 32;
    }
    if (e < end) {
        const int rem = end - e;
        const int idx = e + lane;
        int sv = g_esrc[idx < end ? idx : end - 1];
        const int steps = (rem + 3) >> 2;
        for (int i = 0; i < steps; i++) {
            int s = __shfl_sync(0xffffffffu, sv, 4 * i + slot);
            float4 v = *(const float4*)&g_h1[(size_t)s * U + 4 * q];
            if (4 * i + slot < rem) { a4.x += v.x; a4.y += v.y; a4.z += v.z; a4.w += v.w; }
        }
    }
#pragma unroll
    for (int o = 8; o <= 16; o <<= 1) {
        a4.x += __shfl_xor_sync(0xffffffffu, a4.x, o);
        a4.y += __shfl_xor_sync(0xffffffffu, a4.y, o);
        a4.z += __shfl_xor_sync(0xffffffffu, a4.z, o);
        a4.w += __shfl_xor_sync(0xffffffffu, a4.w, o);
    }

    const int srcl = lane >> 2;
    float cx = __shfl_sync(0xffffffffu, a4.x, srcl);
    float cy = __shfl_sync(0xffffffffu, a4.y, srcl);
    float cz = __shfl_sync(0xffffffffu, a4.z, srcl);
    float cw = __shfl_sync(0xffffffffu, a4.w, srcl);
    const int comp = lane & 3;
    float accf = (comp == 0) ? cx : (comp == 1) ? cy : (comp == 2) ? cz : cw;

    const float v = fmaxf(accf * g_invin[n] + b1[lane], 0.f);

    float o0 = 0.f, o1 = 0.f;
#pragma unroll
    for (int k = 0; k < U; k++) {
        float h = __shfl_sync(0xffffffffu, v, k);
        o0 += h * sW2[k * C + lane];
        if (lane < 8) o1 += h * sW2[k * C + 32 + lane];
    }
    const float so = g_invout[n];
    g_h2[(size_t)n * C + lane] = o0 * so;
    if (lane < 8) g_h2[(size_t)n * C + 32 + lane] = o1 * so;
}

// ---------------------------------------------------------------------------
// Aggregation layer 2 (R11 structure, unchanged).
__global__ void agg2_kernel(float* __restrict__ out, const float* __restrict__ b2) {
    const int n = (blockIdx.x * blockDim.x + threadIdx.x) >> 5;
    const int lane = threadIdx.x & 31;
    if (n >= N_NODES) return;
    const int start = g_off[n], end = g_off[n + 1];
    const bool act = lane < 20;

    float ax = 0.f, ay = 0.f;
    int e = start;
    while (e + 32 <= end) {
        int sv = g_esrc[e + lane];
#pragma unroll
        for (int i = 0; i < 32; i++) {
            int s = __shfl_sync(0xffffffffu, sv, i);
            if (act) {
                float2 v = *(const float2*)&g_h2[(size_t)s * C + 2 * lane];
                ax += v.x; ay += v.y;
            }
        }
        e += 32;
    }
    if (e < end) {
        int rem = end - e;
        int sv = (lane < rem) ? g_esrc[e + lane] : 0;
        for (int i = 0; i < rem; i++) {
            int s = __shfl_sync(0xffffffffu, sv, i);
            if (act) {
                float2 v = *(const float2*)&g_h2[(size_t)s * C + 2 * lane];
                ax += v.x; ay += v.y;
            }
        }
    }

    const float inv = g_invin[n];
    const float NEG_INF = __int_as_float(0xff800000);
    float v0 = act ? (ax * inv + b2[2 * lane])     : NEG_INF;
    float v1 = act ? (ay * inv + b2[2 * lane + 1]) : NEG_INF;

    float m = fmaxf(v0, v1);
#pragma unroll
    for (int o = 16; o; o >>= 1) m = fmaxf(m, __shfl_xor_sync(0xffffffffu, m, o));
    float se = act ? (expf(v0 - m) + expf(v1 - m)) : 0.f;
#pragma unroll
    for (int o = 16; o; o >>= 1) se += __shfl_xor_sync(0xffffffffu, se, o);
    const float ls = logf(se);

    if (act) {
        float2 o;
        o.x = v0 - m - ls;
        o.y = v1 - m - ls;
        *(float2*)&out[(size_t)n * C + 2 * lane] = o;
    }
}

// ---------------------------------------------------------------------------
extern "C" void kernel_launch(void* const* d_in, const int* in_sizes, int n_in,
                              void* d_out, int out_size) {
    const float* x   = (const float*)d_in[0];
    const float* W1  = (const float*)d_in[1];
    const float* b1  = (const float*)d_in[2];
    const float* W2  = (const float*)d_in[3];
    const float* b2  = (const float*)d_in[4];
    const int*   src = (const int*)d_in[5];
    const int*   dst = (const int*)d_in[6];
    float* out = (float*)d_out;

    zero_deg_kernel<<<(N_NODES + 255) / 256, 256>>>();
    hist_kernel<<<(N_EDGES + 255) / 256, 256>>>(src, dst);
    invsqrt_kernel<<<(N_NODES + 255) / 256, 256>>>();
    gemm1_kernel<<<(N_NODES + TILE_N - 1) / TILE_N, 128>>>(x, W1);   // slot #4 -> profiled
    scan_part_kernel<<<SCAN_NB, SCAN_CH>>>();
    scan_mid_kernel<<<1, 256>>>();
    scan_write_kernel<<<SCAN_NB, SCAN_CH>>>();
    reorder_kernel<<<(N_EDGES + 255) / 256, 256>>>(src, dst);
    agg1_kernel<<<(N_NODES * 32 + 255) / 256, 256>>>(b1, W2);
    agg2_kernel<<<(N_NODES * 32 + 255) / 256, 256>>>(out, b2);
}